// round 1
// baseline (speedup 1.0000x reference)
#include <cuda_runtime.h>
#include <math.h>

#define NUM      512
#define DH       64
#define EMAX     4096
#define MAIN_N   10
#define LDH      68          // padded row stride (floats): 272B = 16B-aligned, bank-skewed
#define THREADS  512

// ------------------------- device scratch (no allocs allowed) ----------------
__device__ float g_dinv[NUM];
__device__ int   g_ptr[NUM + 1];
__device__ int   g_csr_row[EMAX];
__device__ float g_csr_coef[EMAX];
__device__ float g_EW1[NUM * DH];

// ------------------------- packed f32x2 helpers (sm_100+) --------------------
static __device__ __forceinline__ unsigned long long pk2(float x, float y){
    unsigned long long r;
    asm("mov.b64 %0, {%1,%2};" : "=l"(r) : "f"(x), "f"(y));
    return r;
}
static __device__ __forceinline__ void upk2(unsigned long long v, float& x, float& y){
    asm("mov.b64 {%0,%1}, %2;" : "=f"(x), "=f"(y) : "l"(v));
}
static __device__ __forceinline__ unsigned long long ffma2(unsigned long long a,
                                                           unsigned long long b,
                                                           unsigned long long c){
    unsigned long long d;
    asm("fma.rn.f32x2 %0, %1, %2, %3;" : "=l"(d) : "l"(a), "l"(b), "l"(c));
    return d;
}

// ------------------------- prep 1: degree, dinv, CSR ptr ---------------------
__global__ void prep_deg(const int* __restrict__ ecol, int E){
    __shared__ int deg[NUM];
    int t = threadIdx.x;
    deg[t] = 0;
    __syncthreads();
    for (int e = t; e < E; e += NUM) atomicAdd(&deg[ecol[e]], 1);
    __syncthreads();
    int dg = deg[t];
    g_dinv[t] = dg > 0 ? rsqrtf((float)dg) : 0.f;
    __syncthreads();
    if (t == 0){
        int s = 0;
        for (int n = 0; n < NUM; n++){ g_ptr[n] = s; s += deg[n]; }
        g_ptr[NUM] = s;
    }
}

// ------------------------- prep 2: stable col-sorted CSR ---------------------
// thread per column; stable (original edge order) => deterministic fp sums
__global__ void prep_csr(const int* __restrict__ erow, const int* __restrict__ ecol, int E){
    int n = blockIdx.x * blockDim.x + threadIdx.x;   // 0..NUM-1
    int p = g_ptr[n];
    float dn = g_dinv[n];
    for (int e = 0; e < E; e++){
        if (ecol[e] == n){
            int r = erow[e];
            g_csr_row[p]  = r;
            g_csr_coef[p] = dn * g_dinv[r];
            p++;
        }
    }
}

// ------------------------- prep 3: EW1 = embedding @ W1 ----------------------
__global__ void prep_ew1(const float* __restrict__ emb, const float* __restrict__ W1){
    int i = blockIdx.x * blockDim.x + threadIdx.x;   // n*64 + d
    int n = i >> 6, d = i & 63;
    float acc = 0.f;
#pragma unroll
    for (int k = 0; k < DH; k++) acc += emb[n * DH + k] * W1[k * DH + d];
    g_EW1[i] = acc;
}

// ------------------------- fused GCN mega-kernel (one CTA per batch) ---------
__global__ void __launch_bounds__(THREADS, 1)
gcn_mega(const float* __restrict__ x,
         const float* __restrict__ b1,
         const float* __restrict__ W2,
         const float* __restrict__ b2,
         const float* __restrict__ W3,
         const float* __restrict__ b3,
         float* __restrict__ out)
{
    extern __shared__ float sm[];
    float* h   = sm;                     // [NUM][LDH]  agg1 -> h1 -> t2 (in place)
    float* agg = h   + NUM * LDH;        // [256][LDH]  layer-2 tile
    float* xs  = agg + 256 * LDH;        // [NUM]
    float* t3  = xs  + NUM;              // [NUM]
    float* lg  = t3  + NUM;              // [NUM]

    const int t  = threadIdx.x;
    const int b  = blockIdx.x;
    const int dp = t & 31;               // dim-pair 0..31 (agg phases: warp per node)
    const int gw = t >> 5;               // warp id 0..15
    const int d  = t & 63;               // dim 0..63 (transform)
    const int g8 = t >> 6;               // group 0..7

    xs[t] = x[b * NUM + t];
    __syncthreads();

    // ---- layer 1: agg1[n,:] = sum_e coef*x[row]*EW1[row,:]; +b1; relu -------
    {
        const float2* ew = (const float2*)g_EW1;
        float b1x = b1[2 * dp], b1y = b1[2 * dp + 1];
        for (int n = gw; n < NUM; n += 16){
            int e0 = g_ptr[n], e1 = g_ptr[n + 1];
            float a0 = 0.f, a1 = 0.f;
#pragma unroll 4
            for (int e = e0; e < e1; e++){
                int   r = g_csr_row[e];
                float c = g_csr_coef[e] * xs[r];
                float2 w = ew[r * 32 + dp];
                a0 += c * w.x;
                a1 += c * w.y;
            }
            h[n * LDH + 2 * dp]     = fmaxf(a0 + b1x, 0.f);
            h[n * LDH + 2 * dp + 1] = fmaxf(a1 + b1y, 0.f);
        }
    }
    __syncthreads();

    // ---- in-place row-local transform: h <- h @ W2 (packed f32x2) -----------
    {
        unsigned long long w2p[32];      // W2 column d, k packed in pairs
#pragma unroll
        for (int j = 0; j < 32; j++)
            w2p[j] = pk2(W2[(2 * j) * DH + d], W2[(2 * j + 1) * DH + d]);

#pragma unroll 1
        for (int chunk = 0; chunk < 4; chunk++){
            float res[16];
#pragma unroll
            for (int i = 0; i < 16; i++){
                int n = g8 + 8 * (chunk * 16 + i);
                const longlong2* hp = (const longlong2*)(h + n * LDH);
                unsigned long long acc0 = pk2(0.f, 0.f);
                unsigned long long acc1 = pk2(0.f, 0.f);
#pragma unroll
                for (int j = 0; j < 16; j++){
                    longlong2 hv = hp[j];
                    acc0 = ffma2((unsigned long long)hv.x, w2p[2 * j],     acc0);
                    acc1 = ffma2((unsigned long long)hv.y, w2p[2 * j + 1], acc1);
                }
                float s0, s1, s2, s3;
                upk2(acc0, s0, s1);
                upk2(acc1, s2, s3);
                res[i] = (s0 + s2) + (s1 + s3);
            }
            __syncthreads();             // all reads of these rows done
#pragma unroll
            for (int i = 0; i < 16; i++)
                h[(g8 + 8 * (chunk * 16 + i)) * LDH + d] = res[i];
            __syncthreads();             // writes visible before next chunk
        }
    }

    // ---- layer 2 (two 256-node tiles) + per-row dot with W3 -----------------
    {
        float b2x = b2[2 * dp], b2y = b2[2 * dp + 1];
#pragma unroll 1
        for (int T = 0; T < 2; T++){
            for (int nn = gw; nn < 256; nn += 16){
                int n  = T * 256 + nn;
                int e0 = g_ptr[n], e1 = g_ptr[n + 1];
                float a0 = 0.f, a1 = 0.f;
#pragma unroll 4
                for (int e = e0; e < e1; e++){
                    int   r = g_csr_row[e];
                    float c = g_csr_coef[e];
                    float2 hv = *(const float2*)(h + r * LDH + 2 * dp);
                    a0 += c * hv.x;
                    a1 += c * hv.y;
                }
                agg[nn * LDH + 2 * dp]     = fmaxf(a0 + b2x, 0.f);
                agg[nn * LDH + 2 * dp + 1] = fmaxf(a1 + b2y, 0.f);
            }
            __syncthreads();
            if (t < 256){
                float a = 0.f;
#pragma unroll
                for (int k = 0; k < DH; k++) a += agg[t * LDH + k] * W3[k];
                t3[T * 256 + t] = a;
            }
            __syncthreads();
        }
    }

    // ---- layer 3 aggregation: logits ----------------------------------------
    {
        float a = b3[0];
        int e0 = g_ptr[t], e1 = g_ptr[t + 1];
        for (int e = e0; e < e1; e++)
            a += g_csr_coef[e] * t3[g_csr_row[e]];
        lg[t] = a;
    }
    __syncthreads();

    // ---- softmax over [0,10), sigmoid elsewhere ------------------------------
    float v = lg[t];
    if (t < 32){
        float xv = (t < MAIN_N) ? v : -INFINITY;
        float m = xv;
#pragma unroll
        for (int o = 16; o > 0; o >>= 1) m = fmaxf(m, __shfl_xor_sync(0xffffffffu, m, o));
        float p = (t < MAIN_N) ? expf(xv - m) : 0.f;
        float s = p;
#pragma unroll
        for (int o = 16; o > 0; o >>= 1) s += __shfl_xor_sync(0xffffffffu, s, o);
        if (t < MAIN_N) out[b * NUM + t] = p / s;
    }
    if (t >= MAIN_N) out[b * NUM + t] = 1.f / (1.f + expf(-v));
}

// ------------------------- launcher ------------------------------------------
extern "C" void kernel_launch(void* const* d_in, const int* in_sizes, int n_in,
                              void* d_out, int out_size)
{
    const float* x    = (const float*)d_in[0];
    const float* emb  = (const float*)d_in[1];
    const float* W1   = (const float*)d_in[2];
    const float* b1   = (const float*)d_in[3];
    const float* W2   = (const float*)d_in[4];
    const float* b2   = (const float*)d_in[5];
    const float* W3   = (const float*)d_in[6];
    const float* b3   = (const float*)d_in[7];
    const int*  erow  = (const int*)d_in[8];
    const int*  ecol  = (const int*)d_in[9];
    float* out = (float*)d_out;

    const int E = in_sizes[8];
    const int B = in_sizes[0] / NUM;

    const int SMEM_BYTES = (NUM * LDH + 256 * LDH + 3 * NUM) * (int)sizeof(float); // 215040

    cudaFuncSetAttribute(gcn_mega, cudaFuncAttributeMaxDynamicSharedMemorySize, SMEM_BYTES);

    prep_deg<<<1, NUM>>>(ecol, E);
    prep_csr<<<NUM / 128, 128>>>(erow, ecol, E);
    prep_ew1<<<(NUM * DH) / 256, 256>>>(emb, W1);
    gcn_mega<<<B, THREADS, SMEM_BYTES>>>(x, b1, W2, b2, W3, b3, out);

    (void)n_in; (void)out_size;
}

// round 2
// speedup vs baseline: 1.3467x; 1.3467x over previous
#include <cuda_runtime.h>
#include <math.h>

#define NUM      512
#define DH       64
#define EMAX     4096
#define MAIN_N   10
#define LDH      68          // padded row stride (floats)
#define THREADS  512

// ------------------------- device scratch (no allocs allowed) ----------------
__device__ int2  g_csr[EMAX];          // {row, coef bits} col-sorted, stable
__device__ int   g_ptr[NUM + 1];
__device__ float g_EW1[NUM * DH];

// ------------------------- packed f32x2 helpers (sm_100+) --------------------
static __device__ __forceinline__ unsigned long long pk2(float x, float y){
    unsigned long long r;
    asm("mov.b64 %0, {%1,%2};" : "=l"(r) : "f"(x), "f"(y));
    return r;
}
static __device__ __forceinline__ void upk2(unsigned long long v, float& x, float& y){
    asm("mov.b64 {%0,%1}, %2;" : "=f"(x), "=f"(y) : "l"(v));
}
static __device__ __forceinline__ unsigned long long ffma2(unsigned long long a,
                                                           unsigned long long b,
                                                           unsigned long long c){
    unsigned long long d;
    asm("fma.rn.f32x2 %0, %1, %2, %3;" : "=l"(d) : "l"(a), "l"(b), "l"(c));
    return d;
}

// ------------------------- prep: EW1 = embedding @ W1 (wide) -----------------
__global__ void prep_ew1(const float* __restrict__ emb, const float* __restrict__ W1){
    int i = blockIdx.x * blockDim.x + threadIdx.x;   // n*64 + d
    int n = i >> 6, d = i & 63;
    float acc = 0.f;
#pragma unroll
    for (int k = 0; k < DH; k++) acc += emb[n * DH + k] * W1[k * DH + d];
    g_EW1[i] = acc;
}

// ------------------------- prep: graph -> stable col-sorted CSR (1 CTA) ------
__global__ void __launch_bounds__(NUM)
prep_graph(const int* __restrict__ erow, const int* __restrict__ ecol, int E){
    __shared__ int   rs[EMAX];
    __shared__ int   cs[EMAX];
    __shared__ int   deg[NUM];
    __shared__ float dinv[NUM];
    __shared__ int   sptr[NUM + 1];

    const int t = threadIdx.x;
    deg[t] = 0;
    for (int e = t; e < E; e += NUM){ rs[e] = erow[e]; cs[e] = ecol[e]; }
    __syncthreads();
    for (int e = t; e < E; e += NUM) atomicAdd(&deg[cs[e]], 1);
    __syncthreads();
    dinv[t] = deg[t] > 0 ? rsqrtf((float)deg[t]) : 0.f;
    __syncthreads();
    if (t == 0){
        int s = 0;
        for (int n = 0; n < NUM; n++){ sptr[n] = s; s += deg[n]; }
        sptr[NUM] = s;
    }
    __syncthreads();

    // stable fill: thread t scans edges in original order for its column
    int p = sptr[t];
    float dn = dinv[t];
#pragma unroll 8
    for (int e = 0; e < E; e++){
        if (cs[e] == t){
            int r = rs[e];
            g_csr[p] = make_int2(r, __float_as_int(dn * dinv[r]));
            p++;
        }
    }
    g_ptr[t] = sptr[t];
    if (t == 0) g_ptr[NUM] = sptr[NUM];
}

// ------------------------- fused GCN mega-kernel (one CTA per batch) ---------
__global__ void __launch_bounds__(THREADS, 1)
gcn_mega(const float* __restrict__ x,
         const float* __restrict__ b1,
         const float* __restrict__ W2,
         const float* __restrict__ b2,
         const float* __restrict__ W3,
         const float* __restrict__ b3,
         float* __restrict__ out)
{
    extern __shared__ float sm[];
    float* h    = sm;                                 // [NUM][LDH]
    int2*  scsr = (int2*)(sm + NUM * LDH);            // [EMAX]
    float* xs   = sm + NUM * LDH + 2 * EMAX;          // [NUM]
    float* t3   = xs + NUM;                           // [NUM]
    float* lg   = t3 + NUM;                           // [NUM]
    int*   sptr = (int*)(lg + NUM);                   // [NUM+1]

    const int t  = threadIdx.x;
    const int b  = blockIdx.x;
    const int dp = t & 31;               // dim-pair 0..31
    const int gw = t >> 5;               // warp id 0..15
    const int d  = t & 63;               // dim 0..63 (transform)
    const int g8 = t >> 6;               // group 0..7

    // ---- stage per-graph constants into shared --------------------------------
    xs[t] = x[b * NUM + t];
    {
        const int2* gc = g_csr;
        for (int e = t; e < EMAX; e += THREADS) scsr[e] = gc[e];
        if (t <= NUM) sptr[t] = g_ptr[t];
    }
    __syncthreads();

    // ---- layer 1: h[n,:] = relu( sum_e c*x[row]*EW1[row,:] + b1 ) -------------
    {
        const float2* ew = (const float2*)g_EW1;
        float b1x = b1[2 * dp], b1y = b1[2 * dp + 1];
        for (int n = gw; n < NUM; n += 16){
            int e0 = sptr[n], e1 = sptr[n + 1];
            float a0 = 0.f, a1 = 0.f;
#pragma unroll 4
            for (int e = e0; e < e1; e++){
                int2  rc = scsr[e];
                float c  = __int_as_float(rc.y) * xs[rc.x];
                float2 w = ew[rc.x * 32 + dp];
                a0 += c * w.x;
                a1 += c * w.y;
            }
            float2 o;
            o.x = fmaxf(a0 + b1x, 0.f);
            o.y = fmaxf(a1 + b1y, 0.f);
            *(float2*)(h + n * LDH + 2 * dp) = o;
        }
    }
    __syncthreads();

    // ---- in-place row-local transform: h <- h @ W2 (packed f32x2) -------------
    {
        unsigned long long w2p[32];      // W2 column d, k packed in pairs
#pragma unroll
        for (int j = 0; j < 32; j++)
            w2p[j] = pk2(W2[(2 * j) * DH + d], W2[(2 * j + 1) * DH + d]);

#pragma unroll 1
        for (int chunk = 0; chunk < 4; chunk++){
            float res[16];
#pragma unroll
            for (int i = 0; i < 16; i++){
                int n = g8 + 8 * (chunk * 16 + i);
                const longlong2* hp = (const longlong2*)(h + n * LDH);
                unsigned long long acc0 = pk2(0.f, 0.f);
                unsigned long long acc1 = pk2(0.f, 0.f);
#pragma unroll
                for (int j = 0; j < 16; j++){
                    longlong2 hv = hp[j];
                    acc0 = ffma2((unsigned long long)hv.x, w2p[2 * j],     acc0);
                    acc1 = ffma2((unsigned long long)hv.y, w2p[2 * j + 1], acc1);
                }
                float s0, s1, s2, s3;
                upk2(acc0, s0, s1);
                upk2(acc1, s2, s3);
                res[i] = (s0 + s2) + (s1 + s3);
            }
            __syncthreads();             // all reads of these rows done
#pragma unroll
            for (int i = 0; i < 16; i++)
                h[(g8 + 8 * (chunk * 16 + i)) * LDH + d] = res[i];
            __syncthreads();             // writes visible before next chunk
        }
    }

    // ---- layer 2 agg + relu + W3 dot, fused in registers ----------------------
    {
        float b2x = b2[2 * dp], b2y = b2[2 * dp + 1];
        float w3x = W3[2 * dp], w3y = W3[2 * dp + 1];
        for (int n = gw; n < NUM; n += 16){
            int e0 = sptr[n], e1 = sptr[n + 1];
            float a0 = 0.f, a1 = 0.f;
#pragma unroll 4
            for (int e = e0; e < e1; e++){
                int2  rc = scsr[e];
                float c  = __int_as_float(rc.y);
                float2 hv = *(const float2*)(h + rc.x * LDH + 2 * dp);
                a0 += c * hv.x;
                a1 += c * hv.y;
            }
            a0 = fmaxf(a0 + b2x, 0.f);
            a1 = fmaxf(a1 + b2y, 0.f);
            float v = a0 * w3x + a1 * w3y;
#pragma unroll
            for (int o = 16; o > 0; o >>= 1) v += __shfl_xor_sync(0xffffffffu, v, o);
            if (dp == 0) t3[n] = v;
        }
    }
    __syncthreads();

    // ---- layer 3 aggregation: logits -------------------------------------------
    {
        float a = b3[0];
        int e0 = sptr[t], e1 = sptr[t + 1];
#pragma unroll 4
        for (int e = e0; e < e1; e++){
            int2 rc = scsr[e];
            a += __int_as_float(rc.y) * t3[rc.x];
        }
        lg[t] = a;
    }
    __syncthreads();

    // ---- softmax over [0,10), sigmoid elsewhere ---------------------------------
    float v = lg[t];
    if (t < 32){
        float xv = (t < MAIN_N) ? v : -INFINITY;
        float m = xv;
#pragma unroll
        for (int o = 16; o > 0; o >>= 1) m = fmaxf(m, __shfl_xor_sync(0xffffffffu, m, o));
        float p = (t < MAIN_N) ? expf(xv - m) : 0.f;
        float s = p;
#pragma unroll
        for (int o = 16; o > 0; o >>= 1) s += __shfl_xor_sync(0xffffffffu, s, o);
        if (t < MAIN_N) out[b * NUM + t] = p / s;
    }
    if (t >= MAIN_N) out[b * NUM + t] = 1.f / (1.f + expf(-v));
}

// ------------------------- launcher ------------------------------------------
extern "C" void kernel_launch(void* const* d_in, const int* in_sizes, int n_in,
                              void* d_out, int out_size)
{
    const float* x    = (const float*)d_in[0];
    const float* emb  = (const float*)d_in[1];
    const float* W1   = (const float*)d_in[2];
    const float* b1   = (const float*)d_in[3];
    const float* W2   = (const float*)d_in[4];
    const float* b2   = (const float*)d_in[5];
    const float* W3   = (const float*)d_in[6];
    const float* b3   = (const float*)d_in[7];
    const int*  erow  = (const int*)d_in[8];
    const int*  ecol  = (const int*)d_in[9];
    float* out = (float*)d_out;

    const int E = in_sizes[8];
    const int B = in_sizes[0] / NUM;

    // smem: h + csr(int2) + xs + t3 + lg + sptr
    const int SMEM_BYTES = (NUM * LDH + 2 * EMAX + 3 * NUM) * (int)sizeof(float)
                         + (NUM + 1) * (int)sizeof(int);   // ~180 KB

    cudaFuncSetAttribute(gcn_mega, cudaFuncAttributeMaxDynamicSharedMemorySize, SMEM_BYTES);

    prep_ew1<<<(NUM * DH) / 256, 256>>>(emb, W1);
    prep_graph<<<1, NUM>>>(erow, ecol, E);
    gcn_mega<<<B, THREADS, SMEM_BYTES>>>(x, b1, W2, b2, W3, b3, out);

    (void)n_in; (void)out_size;
}